// round 4
// baseline (speedup 1.0000x reference)
#include <cuda_runtime.h>
#include <cstddef>

// Problem constants (fixed shapes)
#define NROWS   131072          // B*T = 64*2048
#define CGROUPS 4
#define DSUB    128             // d = D/C
#define KCODES  128
#define DFULL   512

#define ROWS_PER_BLOCK 128
#define THREADS 256

#define ES_STRIDE 129           // pad 1 -> conflict-free strided-k e loads
#define XS_STRIDE 132           // pad 4 -> float4-aligned rows

// smem layout (float offsets)
#define OFF_ES    0
#define OFF_XS    (KCODES * ES_STRIDE)                      // 16512
#define OFF_E2    (OFF_XS + ROWS_PER_BLOCK * XS_STRIDE)     // 33408
#define OFF_X2    (OFF_E2 + KCODES)                         // 33536
#define OFF_LOSS  (OFF_X2 + ROWS_PER_BLOCK)                 // 33664
#define OFF_BESTK (OFF_LOSS + ROWS_PER_BLOCK)               // 33792 (int)
#define OFF_IDX   (OFF_BESTK + ROWS_PER_BLOCK)              // 33920 (int)
#define SMEM_FLOATS (OFF_IDX + ROWS_PER_BLOCK)              // 34048
#define SMEM_BYTES  (SMEM_FLOATS * 4)                       // 136192

// ---- packed f32x2 helpers (sm_103a FFMA2 path) ----
__device__ __forceinline__ unsigned long long pack2(float a, float b) {
    unsigned long long r;
    asm("mov.b64 %0, {%1, %2};" : "=l"(r)
        : "r"(__float_as_uint(a)), "r"(__float_as_uint(b)));
    return r;
}
__device__ __forceinline__ void unpack2(unsigned long long v, float& lo, float& hi) {
    unsigned a, b;
    asm("mov.b64 {%0, %1}, %2;" : "=r"(a), "=r"(b) : "l"(v));
    lo = __uint_as_float(a);
    hi = __uint_as_float(b);
}
__device__ __forceinline__ void fma2(unsigned long long& d,
                                     unsigned long long a,
                                     unsigned long long b) {
    asm("fma.rn.f32x2 %0, %1, %2, %3;" : "=l"(d) : "l"(a), "l"(b), "l"(d));
}

// XLA-style warp row-reduction: strided partials already in s, then
// shfl_down tree (16,8,4,2,1), true sum valid in lane 0.
__device__ __forceinline__ float xla_warp_tree(float s) {
    s += __shfl_down_sync(0xffffffffu, s, 16);
    s += __shfl_down_sync(0xffffffffu, s, 8);
    s += __shfl_down_sync(0xffffffffu, s, 4);
    s += __shfl_down_sync(0xffffffffu, s, 2);
    s += __shfl_down_sync(0xffffffffu, s, 1);
    return s;
}

__global__ __launch_bounds__(THREADS, 1)
void pvq_kernel(const float* __restrict__ inp,
                const float* __restrict__ emb,
                float* __restrict__ out_q,
                float* __restrict__ out_idx,
                float* __restrict__ out_loss,
                int write_aux)
{
    extern __shared__ float sm[];
    float* es      = sm + OFF_ES;
    float* xs      = sm + OFF_XS;
    float* e2s     = sm + OFF_E2;
    float* x2s     = sm + OFF_X2;
    float* lossacc = sm + OFF_LOSS;
    int*   bestk   = (int*)(sm + OFF_BESTK);
    int*   idxacc  = (int*)(sm + OFF_IDX);

    const int t    = threadIdx.x;
    const int row0 = blockIdx.x * ROWS_PER_BLOCK;
    const int cg   = t & 15;   // code group (codes cg + 16*j)
    const int rg   = t >> 4;   // row group (rows rg*8 .. rg*8+7)
    const int lane = t & 31;
    const int warp = t >> 5;   // 8 warps

    if (t < ROWS_PER_BLOCK) { lossacc[t] = 0.0f; idxacc[t] = 0; }

    int powc = KCODES * KCODES * KCODES;   // 128^3, divided by 128 each group

    for (int c = 0; c < CGROUPS; ++c) {
        // ---- stage embeddings group c into smem ----
        {
            const float4* eg = (const float4*)(emb + (size_t)c * KCODES * DSUB);
            #pragma unroll
            for (int i = 0; i < (KCODES * DSUB / 4) / THREADS; ++i) {  // 16 iters
                int f4 = t + i * THREADS;
                int k  = f4 >> 5, d4 = f4 & 31;
                float4 v = eg[f4];
                float* dst = es + k * ES_STRIDE + 4 * d4;
                dst[0] = v.x; dst[1] = v.y; dst[2] = v.z; dst[3] = v.w;
            }
        }
        // ---- stage x tile (row-major, float4, fully coalesced) ----
        {
            #pragma unroll
            for (int i = 0; i < (ROWS_PER_BLOCK * DSUB / 4) / THREADS; ++i) {  // 16
                int f4 = t + i * THREADS;
                int r  = f4 >> 5, d4 = f4 & 31;
                float4 v = *(const float4*)(inp + (size_t)(row0 + r) * DFULL
                                            + c * DSUB + 4 * d4);
                *(float4*)(xs + r * XS_STRIDE + 4 * d4) = v;
            }
        }
        // ---- e2[k]: XLA row-reduce order — lane-strided partials + shfl tree ----
        {
            #pragma unroll
            for (int it = 0; it < KCODES / 8; ++it) {   // 16 k's per warp
                int k = warp * 16 + it;
                const float* er = emb + ((size_t)c * KCODES + k) * DSUB;
                float s = 0.0f;
                #pragma unroll
                for (int i = 0; i < 4; ++i) {
                    float v = er[lane + 32 * i];
                    s = fmaf(v, v, s);
                }
                s = xla_warp_tree(s);
                if (lane == 0) e2s[k] = s;
            }
        }
        __syncthreads();

        // ---- x2[r]: same XLA warp pattern, from smem tile ----
        {
            #pragma unroll
            for (int it = 0; it < ROWS_PER_BLOCK / 8; ++it) {  // 16 rows per warp
                int r = warp * 16 + it;
                const float* xr = xs + r * XS_STRIDE;
                float s = 0.0f;
                #pragma unroll
                for (int i = 0; i < 4; ++i) {
                    float v = xr[lane + 32 * i];
                    s = fmaf(v, v, s);
                }
                s = xla_warp_tree(s);
                if (lane == 0) x2s[r] = s;
            }
        }

        // ---- main GEMM: dots for 8 rows (4 f32x2 pairs) x 8 codes per thread ----
        // Each (row,code) accumulator is an independent sequential fma chain over
        // d ascending — bitwise identical to cuBLAS SIMT sgemm accumulation.
        unsigned long long acc[4][8];
        #pragma unroll
        for (int p = 0; p < 4; ++p)
            #pragma unroll
            for (int j = 0; j < 8; ++j) acc[p][j] = 0ull;

        const float* xbase = xs + (rg * 8) * XS_STRIDE;
        const float* ebase = es + cg * ES_STRIDE;

        #pragma unroll 2
        for (int dd = 0; dd < DSUB; ++dd) {
            unsigned long long xp[4];
            #pragma unroll
            for (int p = 0; p < 4; ++p) {
                float xa = xbase[(2 * p)     * XS_STRIDE + dd];
                float xb = xbase[(2 * p + 1) * XS_STRIDE + dd];
                xp[p] = pack2(xa, xb);
            }
            #pragma unroll
            for (int j = 0; j < 8; ++j) {
                float ev = ebase[(size_t)j * 16 * ES_STRIDE + dd];
                unsigned long long ep = pack2(ev, ev);
                #pragma unroll
                for (int p = 0; p < 4; ++p) fma2(acc[p][j], xp[p], ep);
            }
        }
        __syncthreads();   // x2s visible to all

        // ---- scores + argmin, replicating reference rounding:
        //      tmp = f32(x2 + e2_k); s = f32(tmp - 2*dot)  (2*dot exact) ----
        float e2r[8];
        #pragma unroll
        for (int j = 0; j < 8; ++j) e2r[j] = e2s[cg + 16 * j];

        #pragma unroll
        for (int p = 0; p < 4; ++p) {
            #pragma unroll
            for (int h = 0; h < 2; ++h) {
                int r = rg * 8 + 2 * p + h;
                float x2v = x2s[r];
                float bs = __int_as_float(0x7f800000);  // +inf
                int   bk = 0;
                #pragma unroll
                for (int j = 0; j < 8; ++j) {
                    float lo, hi;
                    unpack2(acc[p][j], lo, hi);
                    float dot = h ? hi : lo;
                    float tmp = x2v + e2r[j];          // f32 round
                    float s   = tmp - 2.0f * dot;      // 2*dot exact, one round
                    if (s < bs) { bs = s; bk = cg + 16 * j; }  // keeps smallest k
                }
                #pragma unroll
                for (int off = 8; off >= 1; off >>= 1) {
                    float os = __shfl_xor_sync(0xffffffffu, bs, off);
                    int   ok = __shfl_xor_sync(0xffffffffu, bk, off);
                    if (os < bs || (os == bs && ok < bk)) { bs = os; bk = ok; }
                }
                if (cg == 0) {
                    bestk[r]  = bk;
                    idxacc[r] += bk * powc;
                }
            }
        }
        __syncthreads();   // bestk visible

        // ---- epilogue: gather chosen code, quantized_sg, per-row loss partial ----
        #pragma unroll
        for (int i = 0; i < 16; ++i) {
            int f4 = t + i * THREADS;
            int r = f4 >> 5, d4 = f4 & 31, dd = 4 * d4;   // whole warp shares r
            int k = bestk[r];
            const float* ep_ = es + k * ES_STRIDE + dd;
            float4 xv = *(const float4*)(xs + r * XS_STRIDE + dd);

            float d0 = ep_[0] - xv.x;
            float d1 = ep_[1] - xv.y;
            float d2_ = ep_[2] - xv.z;
            float d3 = ep_[3] - xv.w;
            float part = d0 * d0;
            part = fmaf(d1, d1, part);
            part = fmaf(d2_, d2_, part);
            part = fmaf(d3, d3, part);

            float4 qv;                       // x + (q - x), replicating reference
            qv.x = xv.x + d0; qv.y = xv.y + d1;
            qv.z = xv.z + d2_; qv.w = xv.w + d3;
            *(float4*)(out_q + (size_t)(row0 + r) * DFULL + c * DSUB + dd) = qv;

            #pragma unroll
            for (int off = 16; off >= 1; off >>= 1)
                part += __shfl_xor_sync(0xffffffffu, part, off);
            if (lane == 0) lossacc[r] += part;
        }
        powc >>= 7;  // /128
        __syncthreads();
    }

    if (write_aux && t < ROWS_PER_BLOCK) {
        int n = row0 + t;
        out_idx[n] = (float)idxacc[t];
        float d2 = lossacc[t];
        out_loss[n] = d2 + 0.25f * d2;   // q_latent + 0.25*e_latent
    }
}

extern "C" void kernel_launch(void* const* d_in, const int* in_sizes, int n_in,
                              void* d_out, int out_size) {
    const float* inp = (const float*)d_in[0];   // inputs (64,2048,512) f32
    const float* emb = (const float*)d_in[1];   // embeddings (4,128,128) f32
    float* out = (float*)d_out;

    const long long QN = (long long)NROWS * DFULL;
    int write_aux = ((long long)out_size >= QN + 2LL * NROWS) ? 1 : 0;
    float* out_q    = out;
    float* out_idx  = out + QN;
    float* out_loss = out + QN + NROWS;

    cudaFuncSetAttribute(pvq_kernel,
                         cudaFuncAttributeMaxDynamicSharedMemorySize, SMEM_BYTES);
    pvq_kernel<<<NROWS / ROWS_PER_BLOCK, THREADS, SMEM_BYTES>>>(
        inp, emb, out_q, out_idx, out_loss, write_aux);
}